// round 11
// baseline (speedup 1.0000x reference)
#include <cuda_runtime.h>
#include <cuda_bf16.h>
#include <cstdint>

#define MAXL   16
#define S      32         // slices per request (16 KB each for V=128000)
#define TPB    128
#define NCH    4          // TMA chunks per slice (pipelined)
#define MAXB   1024
#define MAXNT  2048
#define BUF_F4 1024       // smem staging (float4) = 16 KB

// Zero-initialized scratch; g_count self-resets -> graph-replay safe.
__device__ unsigned long long g_slot[MAXB * S];
__device__ int                g_count[MAXB];
__device__ int4               g_meta[MAXB];   // x=rejected, y=rec_row, z=write_col

// ---------------------------------------------------------------------------
// Kernel A: ONE block. All token gathers in parallel, per-request scan,
// writes meta + base output rows. (~1.3 us measured)
// ---------------------------------------------------------------------------
__global__ void __launch_bounds__(512)
scan_kernel(const float* __restrict__ draft_probs,
            const float* __restrict__ target_probs,
            const float* __restrict__ uniform_probs,
            const int*   __restrict__ ids,
            const int*   __restrict__ cu,
            const int*   __restrict__ bonus,
            float*       __restrict__ out,
            int V, int NT, int B, int L)
{
    __shared__ float s_r[MAXNT], s_u[MAXNT];
    __shared__ unsigned char s_ok[MAXNT];
    __shared__ int   s_d[MAXNT];
    __shared__ int   s_cu[MAXB];
    const int tid = threadIdx.x;

    for (int t = tid; t < B; t += blockDim.x) s_cu[t] = __ldg(&cu[t]);
    for (int t = tid; t < NT && t < MAXNT; t += blockDim.x) {
        int d = __ldg(&ids[t]);
        float tp = __ldg(&target_probs[(long long)t * V + d]);
        float dv = __ldg(&draft_probs [(long long)t * V + d]);
        s_d[t]  = d;
        s_r[t]  = (dv > 0.0f) ? (tp / dv) : 1.0f;
        s_u[t]  = __ldg(&uniform_probs[t]);
        s_ok[t] = (dv > 0.0f) ? 1 : 0;
    }
    __syncthreads();

    for (int b = tid; b < B; b += blockDim.x) {
        int prev = b ? s_cu[b - 1] : 0;
        int nd   = s_cu[b] - prev;
        int n    = nd < L ? nd : L;
        float pi = 1.0f, U = 1.0f;
        int last = -1;
        for (int i = 0; i < n; i++) {
            int t = prev + i;
            pi = fminf(pi * s_r[t], 1.0f);
            U *= s_u[t];
            if (s_ok[t] && pi >= U) last = i;
        }
        int rejected = (nd > 0) && (last != nd - 1);
        int rr = prev + last + 1;
        rr = max(0, min(rr, NT - 1));
        int wc = rejected ? (last + 1) : n;
        g_meta[b] = make_int4(rejected, rr, wc, 0);
        for (int c = 0; c <= L; c++) {
            int val = (c < L && c <= last && (prev + c) < MAXNT) ? s_d[prev + c] : -1;
            if (c == wc) val = rejected ? -1 : __ldg(&bonus[b]);
            out[b * (L + 1) + c] = (float)val;
        }
    }
}

// ---------------------------------------------------------------------------
// Kernel B: sliced argmax. NCH pipelined TMA bulk copies per block; compute
// on chunk j overlaps delivery of chunks j+1..  High per-SM outstanding bytes
// (13 CTAs x 16 KB) to convert copy latency into bandwidth.
// ---------------------------------------------------------------------------
__global__ void __launch_bounds__(TPB)
argmax_kernel(const float* __restrict__ target_probs,
              float* __restrict__ out, int V, int L)
{
    const int s   = blockIdx.x;
    const int b   = blockIdx.y;
    const int tid = threadIdx.x;

    __shared__ alignas(128) float4 buf[BUF_F4];
    __shared__ alignas(8) unsigned long long mbar[NCH];
    __shared__ float    s_wmax[TPB / 32];
    __shared__ float    s_bmax;
    __shared__ unsigned s_minidx;

    const int4 meta = g_meta[b];
    if (!meta.x) return;

    const int nv4    = V >> 2;
    const int chunk4 = (nv4 + S - 1) / S;
    const int start4 = s * chunk4;
    const int end4   = min(nv4, start4 + chunk4);
    const int n4     = end4 - start4;
    if (n4 <= 0 && !((V & 3) && s == S - 1)) {
        if (tid == 0) {
            g_slot[b * S + s] = 0ull;
            __threadfence();
            int old = atomicAdd(&g_count[b], 1);
            if (old == S - 1) {
                unsigned long long best = 0ull;
                for (int j = 0; j < S; j++) {
                    unsigned long long w = g_slot[b * S + j];
                    if (w > best) best = w;
                }
                out[b * (L + 1) + meta.z] =
                    (float)(int)(0xFFFFFFFFu - (unsigned)(best & 0xFFFFFFFFull));
                g_count[b] = 0;
            }
        }
        return;
    }

    const float4* __restrict__ src4 =
        (const float4*)target_probs + (long long)meta.y * nv4 + start4;
    const float* __restrict__ row = target_probs + (long long)meta.y * V;

    const bool bulk = (n4 > 0) && (n4 <= BUF_F4);
    const int  sub4 = bulk ? ((n4 + NCH - 1) / NCH) : 0;   // float4 per chunk

    unsigned buf_a  = (unsigned)__cvta_generic_to_shared(buf);
    unsigned mbar_a = (unsigned)__cvta_generic_to_shared(mbar);

    if (tid == 0) {
        s_minidx = 0xFFFFFFFFu;
        if (bulk) {
            #pragma unroll
            for (int c = 0; c < NCH; c++)
                asm volatile("mbarrier.init.shared.b64 [%0], %1;"
                             :: "r"(mbar_a + 8u * c), "r"(1) : "memory");
        }
    }
    __syncthreads();

    if (bulk && tid == 0) {
        // Issue ALL chunk copies up-front (max outstanding TMA work).
        #pragma unroll
        for (int c = 0; c < NCH; c++) {
            int c0 = c * sub4;
            int cn = min(sub4, n4 - c0);
            if (cn <= 0) {   // empty chunk: satisfy barrier with 0-byte expect
                asm volatile("mbarrier.arrive.expect_tx.shared.b64 _, [%0], %1;"
                             :: "r"(mbar_a + 8u * c), "r"(0) : "memory");
                continue;
            }
            unsigned bytes = (unsigned)cn * 16u;
            asm volatile("mbarrier.arrive.expect_tx.shared.b64 _, [%0], %1;"
                         :: "r"(mbar_a + 8u * c), "r"(bytes) : "memory");
            asm volatile(
                "cp.async.bulk.shared::cta.global.mbarrier::complete_tx::bytes "
                "[%0], [%1], %2, [%3];"
                :: "r"(buf_a + (unsigned)c0 * 16u), "l"(src4 + c0),
                   "r"(bytes), "r"(mbar_a + 8u * c) : "memory");
        }
    }

    // ---- Pass 1: value max, chunk-pipelined ----
    float m0 = -1.0f, m1 = -1.0f, m2 = -1.0f, m3 = -1.0f;
    if (bulk) {
        for (int c = 0; c < NCH; c++) {
            unsigned done = 0;
            while (!done) {
                asm volatile(
                    "{\n\t.reg .pred p;\n\t"
                    "mbarrier.try_wait.parity.acquire.cta.shared::cta.b64 p, [%1], %2, 0x989680;\n\t"
                    "selp.b32 %0, 1, 0, p;\n\t}"
                    : "=r"(done) : "r"(mbar_a + 8u * c), "r"(0) : "memory");
            }
            int c0 = c * sub4;
            int ce = min(n4, c0 + sub4);
            for (int j = c0 + tid; j < ce; j += TPB) {
                float4 v = buf[j];
                m0 = fmaxf(m0, v.x);
                m1 = fmaxf(m1, v.y);
                m2 = fmaxf(m2, v.z);
                m3 = fmaxf(m3, v.w);
            }
        }
    } else {
        for (int j = tid; j < n4; j += TPB) {
            float4 v = src4[j];
            m0 = fmaxf(m0, v.x);
            m1 = fmaxf(m1, v.y);
            m2 = fmaxf(m2, v.z);
            m3 = fmaxf(m3, v.w);
        }
    }
    float m = fmaxf(fmaxf(m0, m1), fmaxf(m2, m3));
    if ((V & 3) && s == S - 1) {
        for (int i = (nv4 << 2) + tid; i < V; i += TPB)
            m = fmaxf(m, row[i]);
    }
    #pragma unroll
    for (int off = 16; off > 0; off >>= 1)
        m = fmaxf(m, __shfl_down_sync(0xFFFFFFFFu, m, off));
    if ((tid & 31) == 0) s_wmax[tid >> 5] = m;
    __syncthreads();
    if (tid < 32) {
        float v = (tid < (TPB / 32)) ? s_wmax[tid] : -1.0f;
        #pragma unroll
        for (int off = 16; off > 0; off >>= 1)
            v = fmaxf(v, __shfl_down_sync(0xFFFFFFFFu, v, off));
        if (tid == 0) s_bmax = v;
    }
    __syncthreads();

    // ---- Pass 2: first index bit-equal to max (smem-resident if bulk) ----
    const unsigned mbits = __float_as_uint(s_bmax);   // probs >= 0
    unsigned lmin = 0xFFFFFFFFu;
    const float4* base = bulk ? (const float4*)buf : src4;
    for (int j = tid; j < n4; j += TPB) {
        float4 v = base[j];
        unsigned gi = (unsigned)((start4 + j) << 2);
        if (__float_as_uint(v.x) == mbits) lmin = min(lmin, gi);
        if (__float_as_uint(v.y) == mbits) lmin = min(lmin, gi + 1);
        if (__float_as_uint(v.z) == mbits) lmin = min(lmin, gi + 2);
        if (__float_as_uint(v.w) == mbits) lmin = min(lmin, gi + 3);
    }
    if ((V & 3) && s == S - 1) {
        for (int i = (nv4 << 2) + tid; i < V; i += TPB)
            if (__float_as_uint(row[i]) == mbits) lmin = min(lmin, (unsigned)i);
    }
    if (lmin != 0xFFFFFFFFu) atomicMin(&s_minidx, lmin);
    __syncthreads();

    // ---- publish; last block for this request finalizes ----
    if (tid == 0) {
        unsigned long long key =
            ((unsigned long long)mbits << 32) | (0xFFFFFFFFu - s_minidx);
        g_slot[b * S + s] = key;
        __threadfence();
        int old = atomicAdd(&g_count[b], 1);
        if (old == S - 1) {
            unsigned long long best = 0ull;
            for (int j = 0; j < S; j++) {
                unsigned long long w = g_slot[b * S + j];
                if (w > best) best = w;
            }
            int rec = (int)(0xFFFFFFFFu - (unsigned)(best & 0xFFFFFFFFull));
            out[b * (L + 1) + meta.z] = (float)rec;
            g_count[b] = 0;   // self-reset for next replay
        }
    }
}

extern "C" void kernel_launch(void* const* d_in, const int* in_sizes, int n_in,
                              void* d_out, int out_size) {
    const float* draft_probs     = (const float*)d_in[0];
    const float* target_probs    = (const float*)d_in[1];
    const float* uniform_probs   = (const float*)d_in[2];
    const int*   draft_token_ids = (const int*)  d_in[3];
    const int*   cu              = (const int*)  d_in[4];
    const int*   bonus           = (const int*)  d_in[5];
    float*       out             = (float*)d_out;

    const int NT = in_sizes[2];
    const int V  = in_sizes[0] / NT;
    const int B  = in_sizes[4];
    const int L  = out_size / B - 1;

    scan_kernel<<<1, 512>>>(draft_probs, target_probs, uniform_probs,
                            draft_token_ids, cu, bonus, out, V, NT, B, L);
    argmax_kernel<<<dim3(S, B), TPB>>>(target_probs, out, V, L);
}

// round 16
// speedup vs baseline: 1.1213x; 1.1213x over previous
#include <cuda_runtime.h>
#include <cuda_bf16.h>
#include <cstdint>

#define MAXL   16
#define S      8          // slices per request (62.5 KB each for V=128000)
#define TPB    256
#define CH_F4  1024       // 16 KB chunks
#define DEPTH  2          // double buffer
#define MAXB   1024
#define MAXNT  2048

// Zero-initialized scratch; g_count self-resets -> graph-replay safe.
__device__ unsigned long long g_slot[MAXB * S];
__device__ int                g_count[MAXB];
__device__ int4               g_meta[MAXB];   // x=rejected, y=rec_row, z=write_col

// ---------------------------------------------------------------------------
// Kernel A: ONE block. Parallel token gathers + per-request scan; writes meta
// and the base output rows. (~1.3 us)
// ---------------------------------------------------------------------------
__global__ void __launch_bounds__(512)
scan_kernel(const float* __restrict__ draft_probs,
            const float* __restrict__ target_probs,
            const float* __restrict__ uniform_probs,
            const int*   __restrict__ ids,
            const int*   __restrict__ cu,
            const int*   __restrict__ bonus,
            float*       __restrict__ out,
            int V, int NT, int B, int L)
{
    __shared__ float s_r[MAXNT], s_u[MAXNT];
    __shared__ unsigned char s_ok[MAXNT];
    __shared__ int   s_d[MAXNT];
    __shared__ int   s_cu[MAXB];
    const int tid = threadIdx.x;

    for (int t = tid; t < B; t += blockDim.x) s_cu[t] = __ldg(&cu[t]);
    for (int t = tid; t < NT && t < MAXNT; t += blockDim.x) {
        int d = __ldg(&ids[t]);
        float tp = __ldg(&target_probs[(long long)t * V + d]);
        float dv = __ldg(&draft_probs [(long long)t * V + d]);
        s_d[t]  = d;
        s_r[t]  = (dv > 0.0f) ? (tp / dv) : 1.0f;
        s_u[t]  = __ldg(&uniform_probs[t]);
        s_ok[t] = (dv > 0.0f) ? 1 : 0;
    }
    __syncthreads();

    for (int b = tid; b < B; b += blockDim.x) {
        int prev = b ? s_cu[b - 1] : 0;
        int nd   = s_cu[b] - prev;
        int n    = nd < L ? nd : L;
        float pi = 1.0f, U = 1.0f;
        int last = -1;
        for (int i = 0; i < n; i++) {
            int t = prev + i;
            pi = fminf(pi * s_r[t], 1.0f);
            U *= s_u[t];
            if (s_ok[t] && pi >= U) last = i;
        }
        int rejected = (nd > 0) && (last != nd - 1);
        int rr = prev + last + 1;
        rr = max(0, min(rr, NT - 1));
        int wc = rejected ? (last + 1) : n;
        g_meta[b] = make_int4(rejected, rr, wc, 0);
        for (int c = 0; c <= L; c++) {
            int val = (c < L && c <= last && (prev + c) < MAXNT) ? s_d[prev + c] : -1;
            if (c == wc) val = rejected ? -1 : __ldg(&bonus[b]);
            out[b * (L + 1) + c] = (float)val;
        }
    }
}

// ---------------------------------------------------------------------------
// Kernel B: sliced argmax with a double-buffered TMA pipeline. Single pass:
// compute (with index tracking, pure ALU on smem data) overlaps the next
// chunk's bulk copy.
// ---------------------------------------------------------------------------
__global__ void __launch_bounds__(TPB)
argmax_kernel(const float* __restrict__ target_probs,
              float* __restrict__ out, int V, int L)
{
    const int s   = blockIdx.x;
    const int b   = blockIdx.y;
    const int tid = threadIdx.x;

    __shared__ alignas(128) float4 buf[DEPTH][CH_F4];
    __shared__ alignas(8) unsigned long long mbar[DEPTH];
    __shared__ unsigned long long s_warp[TPB / 32];

    const int4 meta = g_meta[b];
    if (!meta.x) return;

    const int nv4    = V >> 2;
    const int chunk4 = (nv4 + S - 1) / S;
    const int start4 = s * chunk4;
    const int end4   = min(nv4, start4 + chunk4);
    const int n4     = end4 - start4;
    const bool tail  = (V & 3) && (s == S - 1);

    const float4* __restrict__ src4 =
        (const float4*)target_probs + (long long)meta.y * nv4 + start4;
    const float* __restrict__ row = target_probs + (long long)meta.y * V;

    unsigned buf_a  = (unsigned)__cvta_generic_to_shared(&buf[0][0]);
    unsigned mbar_a = (unsigned)__cvta_generic_to_shared(mbar);

    const int nch = (n4 + CH_F4 - 1) / CH_F4;

    // Init barriers and issue the first DEPTH copies (single thread).
    if (tid == 0 && nch > 0) {
        #pragma unroll
        for (int i = 0; i < DEPTH; i++)
            asm volatile("mbarrier.init.shared.b64 [%0], %1;"
                         :: "r"(mbar_a + 8u * i), "r"(1) : "memory");
        #pragma unroll
        for (int c = 0; c < DEPTH; c++) {
            if (c >= nch) break;
            int c0 = c * CH_F4;
            unsigned bytes = (unsigned)(min(CH_F4, n4 - c0)) * 16u;
            asm volatile("mbarrier.arrive.expect_tx.shared.b64 _, [%0], %1;"
                         :: "r"(mbar_a + 8u * c), "r"(bytes) : "memory");
            asm volatile(
                "cp.async.bulk.shared::cta.global.mbarrier::complete_tx::bytes "
                "[%0], [%1], %2, [%3];"
                :: "r"(buf_a + (unsigned)c0 * 16u % (DEPTH * CH_F4 * 16u)),
                   "l"(src4 + c0), "r"(bytes), "r"(mbar_a + 8u * c) : "memory");
        }
    }
    __syncthreads();

    // 4 monotonic 32-bit max/index chains (probs >= 0 -> bit order == value
    // order; strict '>' + ascending per-thread index keeps the FIRST max).
    unsigned m0 = 0, m1 = 0, m2 = 0, m3 = 0;
    unsigned i0 = 0xFFFFFFFFu, i1 = 0xFFFFFFFFu, i2 = 0xFFFFFFFFu, i3 = 0xFFFFFFFFu;
    unsigned ph0 = 0, ph1 = 0;

    for (int c = 0; c < nch; c++) {
        const int ibuf = c & (DEPTH - 1);
        unsigned ph = ibuf ? ph1 : ph0;
        unsigned done = 0;
        while (!done) {
            asm volatile(
                "{\n\t.reg .pred p;\n\t"
                "mbarrier.try_wait.parity.acquire.cta.shared::cta.b64 p, [%1], %2, 0x989680;\n\t"
                "selp.b32 %0, 1, 0, p;\n\t}"
                : "=r"(done) : "r"(mbar_a + 8u * ibuf), "r"(ph) : "memory");
        }
        if (ibuf) ph1 ^= 1; else ph0 ^= 1;

        const int c0 = c * CH_F4;
        const int ce = min(n4, c0 + CH_F4);
        for (int j = c0 + tid; j < ce; j += TPB) {
            float4 v = buf[ibuf][j - c0];
            unsigned gi = (unsigned)((start4 + j) << 2);
            unsigned t;
            t = __float_as_uint(v.x); if (t > m0) { m0 = t; i0 = gi;     }
            t = __float_as_uint(v.y); if (t > m1) { m1 = t; i1 = gi + 1; }
            t = __float_as_uint(v.z); if (t > m2) { m2 = t; i2 = gi + 2; }
            t = __float_as_uint(v.w); if (t > m3) { m3 = t; i3 = gi + 3; }
        }
        __syncthreads();                 // all reads of buf[ibuf] complete

        const int nc = c + DEPTH;        // refill this buffer
        if (tid == 0 && nc < nch) {
            int n0 = nc * CH_F4;
            unsigned bytes = (unsigned)(min(CH_F4, n4 - n0)) * 16u;
            asm volatile("mbarrier.arrive.expect_tx.shared.b64 _, [%0], %1;"
                         :: "r"(mbar_a + 8u * ibuf), "r"(bytes) : "memory");
            asm volatile(
                "cp.async.bulk.shared::cta.global.mbarrier::complete_tx::bytes "
                "[%0], [%1], %2, [%3];"
                :: "r"(buf_a + (unsigned)ibuf * CH_F4 * 16u),
                   "l"(src4 + n0), "r"(bytes), "r"(mbar_a + 8u * ibuf) : "memory");
        }
    }

    if (tail) {                          // scalar tail straight from gmem
        for (int i = (nv4 << 2) + tid; i < V; i += TPB) {
            unsigned t = __float_as_uint(row[i]);
            if (t > m0) { m0 = t; i0 = (unsigned)i; }
        }
    }

    // Merge chains -> packed key; block reduce.
    unsigned long long best, k;
    best = ((unsigned long long)m0 << 32) | (0xFFFFFFFFu - i0);
    k    = ((unsigned long long)m1 << 32) | (0xFFFFFFFFu - i1); if (k > best) best = k;
    k    = ((unsigned long long)m2 << 32) | (0xFFFFFFFFu - i2); if (k > best) best = k;
    k    = ((unsigned long long)m3 << 32) | (0xFFFFFFFFu - i3); if (k > best) best = k;

    #pragma unroll
    for (int off = 16; off > 0; off >>= 1) {
        unsigned long long o = __shfl_down_sync(0xFFFFFFFFu, best, off);
        if (o > best) best = o;
    }
    if ((tid & 31) == 0) s_warp[tid >> 5] = best;
    __syncthreads();

    if (tid < 32) {
        unsigned long long v = (tid < (TPB / 32)) ? s_warp[tid] : 0ull;
        #pragma unroll
        for (int off = 16; off > 0; off >>= 1) {
            unsigned long long o = __shfl_down_sync(0xFFFFFFFFu, v, off);
            if (o > v) v = o;
        }
        if (tid == 0) {
            g_slot[b * S + s] = v;       // empty slice publishes 0 (v==0)
            __threadfence();
            int old = atomicAdd(&g_count[b], 1);
            if (old == S - 1) {
                unsigned long long m = 0ull;
                #pragma unroll
                for (int j = 0; j < S; j++) {
                    unsigned long long w = g_slot[b * S + j];
                    if (w > m) m = w;
                }
                int rec = (int)(0xFFFFFFFFu - (unsigned)(m & 0xFFFFFFFFull));
                out[b * (L + 1) + meta.z] = (float)rec;
                g_count[b] = 0;          // self-reset for next replay
            }
        }
    }
}

extern "C" void kernel_launch(void* const* d_in, const int* in_sizes, int n_in,
                              void* d_out, int out_size) {
    const float* draft_probs     = (const float*)d_in[0];
    const float* target_probs    = (const float*)d_in[1];
    const float* uniform_probs   = (const float*)d_in[2];
    const int*   draft_token_ids = (const int*)  d_in[3];
    const int*   cu              = (const int*)  d_in[4];
    const int*   bonus           = (const int*)  d_in[5];
    float*       out             = (float*)d_out;

    const int NT = in_sizes[2];
    const int V  = in_sizes[0] / NT;
    const int B  = in_sizes[4];
    const int L  = out_size / B - 1;

    scan_kernel<<<1, 512>>>(draft_probs, target_probs, uniform_probs,
                            draft_token_ids, cu, bonus, out, V, NT, B, L);
    argmax_kernel<<<dim3(S, B), TPB>>>(target_probs, out, V, L);
}